// round 14
// baseline (speedup 1.0000x reference)
#include <cuda_runtime.h>
#include <cuda_fp16.h>
#include <mma.h>
#include <math.h>

using namespace nvcuda;

#define NMAX 50000
#define EMAX 800000
#define GMAX 1000
#define LEAK 0.01f
#define EPS  1e-5f
#define CDIV(a,b) (((a)+(b)-1)/(b))

// ---------------- scratch ----------------------------------------------------
__device__ float g_bufA[NMAX*128];
__device__ float g_bufB[NMAX*128];
__device__ float g_bufC[NMAX*128];
__device__ __half g_wh[128*128];    // fp16 W1
__device__ __half g_whc[128*128];   // fp16 [Wl | Wr]
__device__ int   g_indeg[NMAX];
__device__ int   g_off[NMAX+1];
__device__ int   g_cur[NMAX];
__device__ int   g_csr[EMAX];
__device__ float g_dinv[NMAX];
__device__ float g_rcnt[NMAX];
__device__ float g_colsum[256];    // L1:0..127  L2:128..191  L3:192..223
__device__ float g_colsq[256];
__device__ float g_pool[GMAX*32];

// ---------------- degree / CSR ----------------------------------------------
__global__ void deg_kernel(const int* __restrict__ dst, int nE) {
    int e = (blockIdx.x * blockDim.x + threadIdx.x) * 4;
#pragma unroll
    for (int i = 0; i < 4; i++)
        if (e + i < nE) atomicAdd(&g_indeg[dst[e + i]], 1);
}

// single-block scan; also zeros stats counters + pool (graph-replay safe)
__global__ void scan_kernel(int n) {
    __shared__ int part[1024];
    int tid = threadIdx.x;
    for (int i = tid; i < 256; i += 1024) { g_colsum[i] = 0.0f; g_colsq[i] = 0.0f; }
    for (int i = tid; i < GMAX * 32; i += 1024) g_pool[i] = 0.0f;
    int chunk = CDIV(n, 1024);
    int start = tid * chunk;
    int end   = min(start + chunk, n);
    int s = 0;
    for (int i = start; i < end; i++) s += g_indeg[i];
    part[tid] = s;
    __syncthreads();
    for (int off = 1; off < 1024; off <<= 1) {
        int v = (tid >= off) ? part[tid - off] : 0;
        __syncthreads();
        part[tid] += v;
        __syncthreads();
    }
    int run = (tid > 0) ? part[tid - 1] : 0;
    for (int i = start; i < end; i++) {
        int d = g_indeg[i];
        g_off[i] = run;
        g_cur[i] = run;
        g_dinv[i] = rsqrtf((float)(d + 1));
        g_rcnt[i] = 1.0f / (float)(d > 0 ? d : 1);
        run += d;
    }
    if (end == n && start < n) g_off[n] = run;
}

__global__ void fill_csr_kernel(const int* __restrict__ src,
                                const int* __restrict__ dst, int nE) {
    int e = (blockIdx.x * blockDim.x + threadIdx.x) * 4;
#pragma unroll
    for (int i = 0; i < 4; i++) {
        if (e + i < nE) {
            int p = atomicAdd(&g_cur[dst[e + i]], 1);
            g_csr[p] = src[e + i];
        }
    }
}

// ---------------- merged fp16 weight conversion ------------------------------
__global__ void conv_kernel(const float* __restrict__ W1, const float* __restrict__ Wl,
                            const float* __restrict__ Wr) {
    int i = blockIdx.x * blockDim.x + threadIdx.x;
    if (i < 128 * 128) {
        g_wh[i] = __float2half_rn(W1[i]);
    } else if (i < 2 * 128 * 128) {
        int j = i - 128 * 128;
        int k = j >> 7, c = j & 127;
        float v = (c < 64) ? Wl[k * 64 + c] : Wr[k * 64 + (c - 64)];
        g_whc[j] = __float2half_rn(v);
    }
}

// ---------------- GEMM1 via tensor cores: Yh = half(X@Wh * dinv) -------------
__global__ void gemm1_wmma(const float* __restrict__ X, const __half* __restrict__ Wh,
                           __half* __restrict__ Yh, int n) {
    __shared__ __half as[32 * 128];
    __shared__ float  cs[32 * 128];
    int tid = threadIdx.x;
    int r0  = blockIdx.x * 32;
    for (int i = tid; i < 1024; i += 256) {
        int row = r0 + (i >> 5);
        int k4  = i & 31;
        float4 v = (row < n) ? ((const float4*)X)[(size_t)row * 32 + k4]
                             : make_float4(0.f, 0.f, 0.f, 0.f);
        __half2 h0 = __floats2half2_rn(v.x, v.y);
        __half2 h1 = __floats2half2_rn(v.z, v.w);
        uint2 u;
        *(__half2*)&u.x = h0;
        *(__half2*)&u.y = h1;
        ((uint2*)as)[i] = u;
    }
    __syncthreads();
    int warp = tid >> 5;
    int rw = warp >> 2, cw = warp & 3;
    wmma::fragment<wmma::matrix_a, 16, 16, 16, __half, wmma::row_major> fa;
    wmma::fragment<wmma::matrix_b, 16, 16, 16, __half, wmma::row_major> fb0, fb1;
    wmma::fragment<wmma::accumulator, 16, 16, 16, float> fc0, fc1;
    wmma::fill_fragment(fc0, 0.0f);
    wmma::fill_fragment(fc1, 0.0f);
    const __half* abase = as + rw * 16 * 128;
#pragma unroll
    for (int k = 0; k < 128; k += 16) {
        wmma::load_matrix_sync(fa, abase + k, 128);
        wmma::load_matrix_sync(fb0, Wh + k * 128 + cw * 32, 128);
        wmma::load_matrix_sync(fb1, Wh + k * 128 + cw * 32 + 16, 128);
        wmma::mma_sync(fc0, fa, fb0, fc0);
        wmma::mma_sync(fc1, fa, fb1, fc1);
    }
    wmma::store_matrix_sync(cs + rw * 16 * 128 + cw * 32,      fc0, 128, wmma::mem_row_major);
    wmma::store_matrix_sync(cs + rw * 16 * 128 + cw * 32 + 16, fc1, 128, wmma::mem_row_major);
    __syncthreads();
    for (int i = tid; i < 2048; i += 256) {
        int row = i >> 6, c2 = i & 63;
        int grow = r0 + row;
        if (grow < n) {
            float d = g_dinv[grow];
            float v0 = cs[row * 128 + c2 * 2 + 0] * d;
            float v1 = cs[row * 128 + c2 * 2 + 1] * d;
            ((__half2*)Yh)[(size_t)grow * 64 + c2] = __floats2half2_rn(v0, v1);
        }
    }
}

// ---------------- dual GEMM (BN1 finalize computed in-block) -----------------
__global__ void dual_gemm_wmma(const float* __restrict__ X, const __half* __restrict__ Whc,
                               const float* __restrict__ gamma, const float* __restrict__ beta,
                               float invn,
                               __half* __restrict__ P, float* __restrict__ Q, int n) {
    __shared__ __half as[32 * 128];
    __shared__ float  cs[32 * 128];
    __shared__ __align__(16) float scF[128];
    __shared__ __align__(16) float shF[128];
    int tid = threadIdx.x;
    int r0  = blockIdx.x * 32;
    if (tid < 128) {
        float m   = g_colsum[tid] * invn;
        float var = g_colsq[tid] * invn - m * m;
        float sc  = gamma[tid] * rsqrtf(var + EPS);
        scF[tid] = sc;
        shF[tid] = beta[tid] - m * sc;
    }
    __syncthreads();
    for (int i = tid; i < 1024; i += 256) {
        int row = r0 + (i >> 5);
        int k4  = i & 31;
        float4 v = (row < n) ? ((const float4*)X)[(size_t)row * 32 + k4]
                             : make_float4(0.f, 0.f, 0.f, 0.f);
        float4 sc = ((const float4*)scF)[k4];
        float4 sh = ((const float4*)shF)[k4];
        float a;
        a = fmaf(v.x, sc.x, sh.x); v.x = (a >= 0.f) ? a : LEAK * a;
        a = fmaf(v.y, sc.y, sh.y); v.y = (a >= 0.f) ? a : LEAK * a;
        a = fmaf(v.z, sc.z, sh.z); v.z = (a >= 0.f) ? a : LEAK * a;
        a = fmaf(v.w, sc.w, sh.w); v.w = (a >= 0.f) ? a : LEAK * a;
        __half2 h0 = __floats2half2_rn(v.x, v.y);
        __half2 h1 = __floats2half2_rn(v.z, v.w);
        uint2 u;
        *(__half2*)&u.x = h0;
        *(__half2*)&u.y = h1;
        ((uint2*)as)[i] = u;
    }
    __syncthreads();
    int warp = tid >> 5;
    int rw = warp >> 2, cw = warp & 3;
    wmma::fragment<wmma::matrix_a, 16, 16, 16, __half, wmma::row_major> fa;
    wmma::fragment<wmma::matrix_b, 16, 16, 16, __half, wmma::row_major> fb0, fb1;
    wmma::fragment<wmma::accumulator, 16, 16, 16, float> fc0, fc1;
    wmma::fill_fragment(fc0, 0.0f);
    wmma::fill_fragment(fc1, 0.0f);
    const __half* abase = as + rw * 16 * 128;
#pragma unroll
    for (int k = 0; k < 128; k += 16) {
        wmma::load_matrix_sync(fa, abase + k, 128);
        wmma::load_matrix_sync(fb0, Whc + k * 128 + cw * 32, 128);
        wmma::load_matrix_sync(fb1, Whc + k * 128 + cw * 32 + 16, 128);
        wmma::mma_sync(fc0, fa, fb0, fc0);
        wmma::mma_sync(fc1, fa, fb1, fc1);
    }
    wmma::store_matrix_sync(cs + rw * 16 * 128 + cw * 32,      fc0, 128, wmma::mem_row_major);
    wmma::store_matrix_sync(cs + rw * 16 * 128 + cw * 32 + 16, fc1, 128, wmma::mem_row_major);
    __syncthreads();
    for (int i = tid; i < 4096; i += 256) {
        int row = i >> 7, c = i & 127;
        int grow = r0 + row;
        if (grow < n) {
            float v = cs[i];
            if (c < 64) P[(size_t)grow * 64 + c] = __float2half_rn(v);
            else        Q[(size_t)grow * 64 + (c - 64)] = v;
        }
    }
}

// ---------------- small GEMM (BN finalize in-block) --------------------------
template <int K, int M, int ROWS, int OFF>
__global__ void gemm_small(const float* __restrict__ X, const float* __restrict__ W,
                           const float* __restrict__ gamma, const float* __restrict__ beta,
                           float invn, float* __restrict__ Y, int n) {
    const int RG  = 128 / M;
    const int BR  = RG * ROWS;
    const int PBR = BR + 4;
    __shared__ float xs[K * PBR];
    __shared__ float scF[K], shF[K];
    int tid = threadIdx.x;
    int r0  = blockIdx.x * BR;
    if (tid < K) {
        float m   = g_colsum[OFF + tid] * invn;
        float var = g_colsq[OFF + tid] * invn - m * m;
        float sc  = gamma[tid] * rsqrtf(var + EPS);
        scF[tid] = sc;
        shF[tid] = beta[tid] - m * sc;
    }
    __syncthreads();
    for (int i = tid; i < BR * K; i += 128) {
        int r = i / K, k = i % K;
        int row = r0 + r;
        float v = (row < n) ? X[row * K + k] : 0.0f;
        v = fmaf(v, scF[k], shF[k]);
        v = (v >= 0.0f) ? v : LEAK * v;
        xs[k * PBR + r] = v;
    }
    __syncthreads();
    int col = tid % M;
    int rg  = tid / M;
    float acc[ROWS];
#pragma unroll
    for (int r = 0; r < ROWS; r++) acc[r] = 0.0f;
#pragma unroll 4
    for (int k = 0; k < K; k++) {
        float w = W[k * M + col];
        const float4* xv = (const float4*)&xs[k * PBR + rg * ROWS];
#pragma unroll
        for (int r4 = 0; r4 < ROWS / 4; r4++) {
            float4 xx = xv[r4];
            acc[r4*4+0] = fmaf(xx.x, w, acc[r4*4+0]);
            acc[r4*4+1] = fmaf(xx.y, w, acc[r4*4+1]);
            acc[r4*4+2] = fmaf(xx.z, w, acc[r4*4+2]);
            acc[r4*4+3] = fmaf(xx.w, w, acc[r4*4+3]);
        }
    }
#pragma unroll
    for (int r = 0; r < ROWS; r++) {
        int row = r0 + rg * ROWS + r;
        if (row < n) Y[row * M + col] = acc[r] * g_dinv[row];
    }
}

// ---------------- CSR gathers: 4 nodes/warp, branch-free predicated loop -----
__device__ __forceinline__ float4 h4_to_f4(uint2 raw) {
    const __half2* hp = (const __half2*)&raw;
    float2 a = __half22float2(hp[0]);
    float2 b = __half22float2(hp[1]);
    return make_float4(a.x, a.y, b.x, b.y);
}

__global__ void gather128_gcn_h(const __half* __restrict__ Hin,
                                float* __restrict__ Hout, int n) {
    int w    = (blockIdx.x * blockDim.x + threadIdx.x) >> 5;
    int lane = threadIdx.x & 31;
    int nb = 4 * w;
    if (nb >= n) return;
    const uint2* H2 = (const uint2*)Hin;
    float4 acc[4];
    int e[4], E[4];
#pragma unroll
    for (int j = 0; j < 4; j++) {
        int node = nb + j;
        bool ok = node < n;
        acc[j] = ok ? h4_to_f4(H2[node * 32 + lane]) : make_float4(0.f, 0.f, 0.f, 0.f);
        e[j] = ok ? g_off[node]     : 0;
        E[j] = ok ? g_off[node + 1] : 0;
    }
    int rem = max(max(E[0]-e[0], E[1]-e[1]), max(E[2]-e[2], E[3]-e[3]));
    for (; rem > 0; rem--) {
        int idx[4];
        float m[4];
#pragma unroll
        for (int j = 0; j < 4; j++) {
            bool a = e[j] < E[j];
            idx[j] = a ? __ldg(&g_csr[e[j]]) : 0;
            m[j]   = a ? 1.0f : 0.0f;
            e[j]  += a ? 1 : 0;
        }
#pragma unroll
        for (int j = 0; j < 4; j++) {
            float4 v = h4_to_f4(H2[idx[j] * 32 + lane]);
            acc[j].x = fmaf(m[j], v.x, acc[j].x);
            acc[j].y = fmaf(m[j], v.y, acc[j].y);
            acc[j].z = fmaf(m[j], v.z, acc[j].z);
            acc[j].w = fmaf(m[j], v.w, acc[j].w);
        }
    }
#pragma unroll
    for (int j = 0; j < 4; j++) {
        int node = nb + j;
        if (node < n) {
            float d = g_dinv[node];
            ((float4*)Hout)[node * 32 + lane] =
                make_float4(acc[j].x * d, acc[j].y * d, acc[j].z * d, acc[j].w * d);
        }
    }
}

__global__ void gather64_sage_h(const __half* __restrict__ P, const float* __restrict__ Q,
                                float* __restrict__ Y, int n) {
    int w    = (blockIdx.x * blockDim.x + threadIdx.x) >> 5;
    int lane = threadIdx.x & 31;
    int nb = 4 * w;
    if (nb >= n) return;
    const __half2* P2 = (const __half2*)P;
    float2 acc[4];
    int e[4], E[4];
#pragma unroll
    for (int j = 0; j < 4; j++) {
        int node = nb + j;
        bool ok = node < n;
        acc[j] = make_float2(0.f, 0.f);
        e[j] = ok ? g_off[node]     : 0;
        E[j] = ok ? g_off[node + 1] : 0;
    }
    int rem = max(max(E[0]-e[0], E[1]-e[1]), max(E[2]-e[2], E[3]-e[3]));
    for (; rem > 0; rem--) {
        int idx[4];
        float m[4];
#pragma unroll
        for (int j = 0; j < 4; j++) {
            bool a = e[j] < E[j];
            idx[j] = a ? __ldg(&g_csr[e[j]]) : 0;
            m[j]   = a ? 1.0f : 0.0f;
            e[j]  += a ? 1 : 0;
        }
#pragma unroll
        for (int j = 0; j < 4; j++) {
            float2 v = __half22float2(P2[idx[j] * 32 + lane]);
            acc[j].x = fmaf(m[j], v.x, acc[j].x);
            acc[j].y = fmaf(m[j], v.y, acc[j].y);
        }
    }
#pragma unroll
    for (int j = 0; j < 4; j++) {
        int node = nb + j;
        if (node < n) {
            float r = g_rcnt[node];
            float2 q = ((const float2*)Q)[node * 32 + lane];
            ((float2*)Y)[node * 32 + lane] =
                make_float2(fmaf(acc[j].x, r, q.x), fmaf(acc[j].y, r, q.y));
        }
    }
}

template <int POOL>
__global__ void gather32_kernel(const float* __restrict__ Hin, float* __restrict__ Hout,
                                const int* __restrict__ batch,
                                const float* __restrict__ b4, int n) {
    int w    = (blockIdx.x * blockDim.x + threadIdx.x) >> 5;
    int lane = threadIdx.x & 31;
    int nb = 4 * w;
    if (nb >= n) return;
    float acc[4];
    int e[4], E[4];
#pragma unroll
    for (int j = 0; j < 4; j++) {
        int node = nb + j;
        bool ok = node < n;
        acc[j] = ok ? Hin[node * 32 + lane] : 0.0f;
        e[j] = ok ? g_off[node]     : 0;
        E[j] = ok ? g_off[node + 1] : 0;
    }
    int rem = max(max(E[0]-e[0], E[1]-e[1]), max(E[2]-e[2], E[3]-e[3]));
    for (; rem > 0; rem--) {
        int idx[4];
        float m[4];
#pragma unroll
        for (int j = 0; j < 4; j++) {
            bool a = e[j] < E[j];
            idx[j] = a ? __ldg(&g_csr[e[j]]) : 0;
            m[j]   = a ? 1.0f : 0.0f;
            e[j]  += a ? 1 : 0;
        }
#pragma unroll
        for (int j = 0; j < 4; j++)
            acc[j] = fmaf(m[j], Hin[idx[j] * 32 + lane], acc[j]);
    }
    float bb = POOL ? b4[lane] : 0.0f;
#pragma unroll
    for (int j = 0; j < 4; j++) {
        int node = nb + j;
        if (node < n) {
            if (POOL) {
                float v = fmaf(acc[j], g_dinv[node], bb);
                float* p = &g_pool[batch[node] * 32 + lane];
                asm volatile("red.global.add.f32 [%0], %1;" :: "l"(p), "f"(v) : "memory");
            } else {
                Hout[node * 32 + lane] = acc[j] * g_dinv[node];
            }
        }
    }
}

// ---------------- batch norm stats -------------------------------------------
template <int C, int OFF>
__global__ void bn_stats_kernel(const float* __restrict__ X, long long total) {
    __shared__ float s1[256];
    __shared__ float s2[256];
    int tid = threadIdx.x;
    float sum = 0.0f, sq = 0.0f;
    for (long long i = (long long)blockIdx.x * 256 + tid; i < total;
         i += (long long)gridDim.x * 256) {
        float v = X[i];
        sum += v; sq += v * v;
    }
    s1[tid] = sum; s2[tid] = sq;
    __syncthreads();
    for (int off = 128; off >= C; off >>= 1) {
        if (tid < off) { s1[tid] += s1[tid + off]; s2[tid] += s2[tid + off]; }
        __syncthreads();
    }
    if (tid < C) {
        atomicAdd(&g_colsum[OFF + tid], s1[tid]);
        atomicAdd(&g_colsq[OFF + tid],  s2[tid]);
    }
}

// ---------------- link -------------------------------------------------------
__global__ void link_kernel(const int* __restrict__ li, float* __restrict__ out, int L) {
    int w = (blockIdx.x * blockDim.x + threadIdx.x) / 32;
    int lane = threadIdx.x & 31;
    if (w >= L) return;
    int a = li[w], b = li[L + w];
    float v = g_pool[a * 32 + lane] * g_pool[b * 32 + lane];
#pragma unroll
    for (int off = 16; off > 0; off >>= 1)
        v += __shfl_xor_sync(0xFFFFFFFFu, v, off);
    if (lane == 0) out[w] = 1.0f / (1.0f + expf(-v));
}

// ---------------- launch -----------------------------------------------------
extern "C" void kernel_launch(void* const* d_in, const int* in_sizes, int n_in,
                              void* d_out, int out_size) {
    int base = 4;
    if (n_in >= 20 && in_sizes[4] == 1) base = 5;

    const float* x    = (const float*)d_in[0];
    const int*   ei   = (const int*)d_in[1];
    const int*   batch= (const int*)d_in[2];
    const int*   li   = (const int*)d_in[3];
    const float* W1   = (const float*)d_in[base + 0];
    const float* g1   = (const float*)d_in[base + 2];
    const float* be1  = (const float*)d_in[base + 3];
    const float* Wl2  = (const float*)d_in[base + 4];
    const float* Wr2  = (const float*)d_in[base + 6];
    const float* g2   = (const float*)d_in[base + 7];
    const float* be2  = (const float*)d_in[base + 8];
    const float* W3   = (const float*)d_in[base + 9];
    const float* g3   = (const float*)d_in[base + 11];
    const float* be3  = (const float*)d_in[base + 12];
    const float* W4   = (const float*)d_in[base + 13];
    const float* b4   = (const float*)d_in[base + 14];
    float* out = (float*)d_out;

    const int N = in_sizes[0] / 128;
    const int E = in_sizes[1] / 2;
    const int L = in_sizes[3] / 2;
    const int* src = ei;
    const int* dst = ei + E;
    const float invN = 1.0f / (float)N;

    float *bufA, *bufB, *bufC;
    int* indeg;
    cudaGetSymbolAddress((void**)&bufA,  g_bufA);
    cudaGetSymbolAddress((void**)&bufB,  g_bufB);
    cudaGetSymbolAddress((void**)&bufC,  g_bufC);
    cudaGetSymbolAddress((void**)&indeg, g_indeg);
    __half *wh, *whc;
    cudaGetSymbolAddress((void**)&wh,  g_wh);
    cudaGetSymbolAddress((void**)&whc, g_whc);
    __half* bufAh = (__half*)bufA;

    // ---- setup ----
    cudaMemsetAsync(indeg, 0, N * sizeof(int));
    deg_kernel<<<CDIV(E, 1024), 256>>>(dst, E);
    scan_kernel<<<1, 1024>>>(N);                           // + zeros stats/pool
    fill_csr_kernel<<<CDIV(E, 1024), 256>>>(src, dst, E);
    conv_kernel<<<CDIV(2 * 128 * 128, 256), 256>>>(W1, Wl2, Wr2);

    int gwarps = CDIV(N, 4);   // 4 nodes per warp

    // ---- Layer 1: GCN(128->128) WMMA ----
    gemm1_wmma<<<CDIV(N, 32), 256>>>(x, wh, bufAh, N);
    gather128_gcn_h<<<CDIV(gwarps * 32, 256), 256>>>(bufAh, bufB, N);
    bn_stats_kernel<128, 0><<<1024, 256>>>(bufB, (long long)N * 128);

    // ---- Layer 2: SAGE(128->64) WMMA (BN1 finalized in-block) ----
    dual_gemm_wmma<<<CDIV(N, 32), 256>>>(bufB, whc, g1, be1, invN, bufAh, bufC, N);
    gather64_sage_h<<<CDIV(gwarps * 32, 256), 256>>>(bufAh, bufC, bufB, N);
    bn_stats_kernel<64, 128><<<1024, 256>>>(bufB, (long long)N * 64);

    // ---- Layer 3: GCN(64->32), BN2 finalized in-block ----
    gemm_small<64, 32, 8, 128><<<CDIV(N, 32), 128>>>(bufB, W3, g2, be2, invN, bufA, N);
    gather32_kernel<0><<<CDIV(gwarps * 32, 256), 256>>>(bufA, bufC, batch, b4, N);
    bn_stats_kernel<32, 192><<<1024, 256>>>(bufC, (long long)N * 32);

    // ---- Layer 4: GCN(32->32), BN3 finalized in-block; pool fused in gather ----
    gemm_small<32, 32, 8, 192><<<CDIV(N, 32), 128>>>(bufC, W4, g3, be3, invN, bufA, N);
    gather32_kernel<1><<<CDIV(gwarps * 32, 256), 256>>>(bufA, bufB, batch, b4, N);

    // ---- link ----
    link_kernel<<<CDIV(L * 32, 256), 256>>>(li, out, L);
}

// round 15
// speedup vs baseline: 1.1683x; 1.1683x over previous
#include <cuda_runtime.h>
#include <cuda_fp16.h>
#include <mma.h>
#include <math.h>

using namespace nvcuda;

#define NMAX 50000
#define EMAX 800000
#define GMAX 1000
#define LEAK 0.01f
#define EPS  1e-5f
#define CDIV(a,b) (((a)+(b)-1)/(b))

// ---------------- scratch ----------------------------------------------------
__device__ float g_bufA[NMAX*128];
__device__ float g_bufB[NMAX*128];
__device__ float g_bufC[NMAX*128];
__device__ __half g_wh[128*128];    // fp16 W1
__device__ __half g_whc[128*128];   // fp16 [Wl | Wr]
__device__ int   g_indeg[NMAX];
__device__ int   g_off[NMAX+1];
__device__ int   g_cur[NMAX];
__device__ int   g_csr[EMAX];
__device__ float g_dinv[NMAX];
__device__ float g_rcnt[NMAX];
__device__ float g_colsum[256];    // L1:0..127  L2:128..191  L3:192..223
__device__ float g_colsq[256];
__device__ float g_pool[GMAX*32];

// ---------------- degree / CSR ----------------------------------------------
__global__ void deg_kernel(const int* __restrict__ dst, int nE) {
    int e = (blockIdx.x * blockDim.x + threadIdx.x) * 4;
#pragma unroll
    for (int i = 0; i < 4; i++)
        if (e + i < nE) atomicAdd(&g_indeg[dst[e + i]], 1);
}

// single-block scan; also zeros stats counters + pool (graph-replay safe)
__global__ void scan_kernel(int n) {
    __shared__ int part[1024];
    int tid = threadIdx.x;
    for (int i = tid; i < 256; i += 1024) { g_colsum[i] = 0.0f; g_colsq[i] = 0.0f; }
    for (int i = tid; i < GMAX * 32; i += 1024) g_pool[i] = 0.0f;
    int chunk = CDIV(n, 1024);
    int start = tid * chunk;
    int end   = min(start + chunk, n);
    int s = 0;
    for (int i = start; i < end; i++) s += g_indeg[i];
    part[tid] = s;
    __syncthreads();
    for (int off = 1; off < 1024; off <<= 1) {
        int v = (tid >= off) ? part[tid - off] : 0;
        __syncthreads();
        part[tid] += v;
        __syncthreads();
    }
    int run = (tid > 0) ? part[tid - 1] : 0;
    for (int i = start; i < end; i++) {
        int d = g_indeg[i];
        g_off[i] = run;
        g_cur[i] = run;
        g_dinv[i] = rsqrtf((float)(d + 1));
        g_rcnt[i] = 1.0f / (float)(d > 0 ? d : 1);
        run += d;
    }
    if (end == n && start < n) g_off[n] = run;
}

__global__ void fill_csr_kernel(const int* __restrict__ src,
                                const int* __restrict__ dst, int nE) {
    int e = (blockIdx.x * blockDim.x + threadIdx.x) * 4;
#pragma unroll
    for (int i = 0; i < 4; i++) {
        if (e + i < nE) {
            int p = atomicAdd(&g_cur[dst[e + i]], 1);
            g_csr[p] = src[e + i];
        }
    }
}

// ---------------- merged fp16 weight conversion ------------------------------
__global__ void conv_kernel(const float* __restrict__ W1, const float* __restrict__ Wl,
                            const float* __restrict__ Wr) {
    int i = blockIdx.x * blockDim.x + threadIdx.x;
    if (i < 128 * 128) {
        g_wh[i] = __float2half_rn(W1[i]);
    } else if (i < 2 * 128 * 128) {
        int j = i - 128 * 128;
        int k = j >> 7, c = j & 127;
        float v = (c < 64) ? Wl[k * 64 + c] : Wr[k * 64 + (c - 64)];
        g_whc[j] = __float2half_rn(v);
    }
}

// ---------------- GEMM1 via tensor cores: Yh = half(X@Wh * dinv) -------------
__global__ void gemm1_wmma(const float* __restrict__ X, const __half* __restrict__ Wh,
                           __half* __restrict__ Yh, int n) {
    __shared__ __half as[32 * 128];
    __shared__ float  cs[32 * 128];
    int tid = threadIdx.x;
    int r0  = blockIdx.x * 32;
    for (int i = tid; i < 1024; i += 256) {
        int row = r0 + (i >> 5);
        int k4  = i & 31;
        float4 v = (row < n) ? ((const float4*)X)[(size_t)row * 32 + k4]
                             : make_float4(0.f, 0.f, 0.f, 0.f);
        __half2 h0 = __floats2half2_rn(v.x, v.y);
        __half2 h1 = __floats2half2_rn(v.z, v.w);
        uint2 u;
        *(__half2*)&u.x = h0;
        *(__half2*)&u.y = h1;
        ((uint2*)as)[i] = u;
    }
    __syncthreads();
    int warp = tid >> 5;
    int rw = warp >> 2, cw = warp & 3;
    wmma::fragment<wmma::matrix_a, 16, 16, 16, __half, wmma::row_major> fa;
    wmma::fragment<wmma::matrix_b, 16, 16, 16, __half, wmma::row_major> fb0, fb1;
    wmma::fragment<wmma::accumulator, 16, 16, 16, float> fc0, fc1;
    wmma::fill_fragment(fc0, 0.0f);
    wmma::fill_fragment(fc1, 0.0f);
    const __half* abase = as + rw * 16 * 128;
#pragma unroll
    for (int k = 0; k < 128; k += 16) {
        wmma::load_matrix_sync(fa, abase + k, 128);
        wmma::load_matrix_sync(fb0, Wh + k * 128 + cw * 32, 128);
        wmma::load_matrix_sync(fb1, Wh + k * 128 + cw * 32 + 16, 128);
        wmma::mma_sync(fc0, fa, fb0, fc0);
        wmma::mma_sync(fc1, fa, fb1, fc1);
    }
    wmma::store_matrix_sync(cs + rw * 16 * 128 + cw * 32,      fc0, 128, wmma::mem_row_major);
    wmma::store_matrix_sync(cs + rw * 16 * 128 + cw * 32 + 16, fc1, 128, wmma::mem_row_major);
    __syncthreads();
    for (int i = tid; i < 2048; i += 256) {
        int row = i >> 6, c2 = i & 63;
        int grow = r0 + row;
        if (grow < n) {
            float d = g_dinv[grow];
            float v0 = cs[row * 128 + c2 * 2 + 0] * d;
            float v1 = cs[row * 128 + c2 * 2 + 1] * d;
            ((__half2*)Yh)[(size_t)grow * 64 + c2] = __floats2half2_rn(v0, v1);
        }
    }
}

// ---------------- dual GEMM (BN1 finalize computed in-block) -----------------
__global__ void dual_gemm_wmma(const float* __restrict__ X, const __half* __restrict__ Whc,
                               const float* __restrict__ gamma, const float* __restrict__ beta,
                               float invn,
                               __half* __restrict__ P, float* __restrict__ Q, int n) {
    __shared__ __half as[32 * 128];
    __shared__ float  cs[32 * 128];
    __shared__ __align__(16) float scF[128];
    __shared__ __align__(16) float shF[128];
    int tid = threadIdx.x;
    int r0  = blockIdx.x * 32;
    if (tid < 128) {
        float m   = g_colsum[tid] * invn;
        float var = g_colsq[tid] * invn - m * m;
        float sc  = gamma[tid] * rsqrtf(var + EPS);
        scF[tid] = sc;
        shF[tid] = beta[tid] - m * sc;
    }
    __syncthreads();
    for (int i = tid; i < 1024; i += 256) {
        int row = r0 + (i >> 5);
        int k4  = i & 31;
        float4 v = (row < n) ? ((const float4*)X)[(size_t)row * 32 + k4]
                             : make_float4(0.f, 0.f, 0.f, 0.f);
        float4 sc = ((const float4*)scF)[k4];
        float4 sh = ((const float4*)shF)[k4];
        float a;
        a = fmaf(v.x, sc.x, sh.x); v.x = (a >= 0.f) ? a : LEAK * a;
        a = fmaf(v.y, sc.y, sh.y); v.y = (a >= 0.f) ? a : LEAK * a;
        a = fmaf(v.z, sc.z, sh.z); v.z = (a >= 0.f) ? a : LEAK * a;
        a = fmaf(v.w, sc.w, sh.w); v.w = (a >= 0.f) ? a : LEAK * a;
        __half2 h0 = __floats2half2_rn(v.x, v.y);
        __half2 h1 = __floats2half2_rn(v.z, v.w);
        uint2 u;
        *(__half2*)&u.x = h0;
        *(__half2*)&u.y = h1;
        ((uint2*)as)[i] = u;
    }
    __syncthreads();
    int warp = tid >> 5;
    int rw = warp >> 2, cw = warp & 3;
    wmma::fragment<wmma::matrix_a, 16, 16, 16, __half, wmma::row_major> fa;
    wmma::fragment<wmma::matrix_b, 16, 16, 16, __half, wmma::row_major> fb0, fb1;
    wmma::fragment<wmma::accumulator, 16, 16, 16, float> fc0, fc1;
    wmma::fill_fragment(fc0, 0.0f);
    wmma::fill_fragment(fc1, 0.0f);
    const __half* abase = as + rw * 16 * 128;
#pragma unroll
    for (int k = 0; k < 128; k += 16) {
        wmma::load_matrix_sync(fa, abase + k, 128);
        wmma::load_matrix_sync(fb0, Whc + k * 128 + cw * 32, 128);
        wmma::load_matrix_sync(fb1, Whc + k * 128 + cw * 32 + 16, 128);
        wmma::mma_sync(fc0, fa, fb0, fc0);
        wmma::mma_sync(fc1, fa, fb1, fc1);
    }
    wmma::store_matrix_sync(cs + rw * 16 * 128 + cw * 32,      fc0, 128, wmma::mem_row_major);
    wmma::store_matrix_sync(cs + rw * 16 * 128 + cw * 32 + 16, fc1, 128, wmma::mem_row_major);
    __syncthreads();
    for (int i = tid; i < 4096; i += 256) {
        int row = i >> 7, c = i & 127;
        int grow = r0 + row;
        if (grow < n) {
            float v = cs[i];
            if (c < 64) P[(size_t)grow * 64 + c] = __float2half_rn(v);
            else        Q[(size_t)grow * 64 + (c - 64)] = v;
        }
    }
}

// ---------------- small GEMM (BN finalize in-block) --------------------------
template <int K, int M, int ROWS, int OFF>
__global__ void gemm_small(const float* __restrict__ X, const float* __restrict__ W,
                           const float* __restrict__ gamma, const float* __restrict__ beta,
                           float invn, float* __restrict__ Y, int n) {
    const int RG  = 128 / M;
    const int BR  = RG * ROWS;
    const int PBR = BR + 4;
    __shared__ float xs[K * PBR];
    __shared__ float scF[K], shF[K];
    int tid = threadIdx.x;
    int r0  = blockIdx.x * BR;
    if (tid < K) {
        float m   = g_colsum[OFF + tid] * invn;
        float var = g_colsq[OFF + tid] * invn - m * m;
        float sc  = gamma[tid] * rsqrtf(var + EPS);
        scF[tid] = sc;
        shF[tid] = beta[tid] - m * sc;
    }
    __syncthreads();
    for (int i = tid; i < BR * K; i += 128) {
        int r = i / K, k = i % K;
        int row = r0 + r;
        float v = (row < n) ? X[row * K + k] : 0.0f;
        v = fmaf(v, scF[k], shF[k]);
        v = (v >= 0.0f) ? v : LEAK * v;
        xs[k * PBR + r] = v;
    }
    __syncthreads();
    int col = tid % M;
    int rg  = tid / M;
    float acc[ROWS];
#pragma unroll
    for (int r = 0; r < ROWS; r++) acc[r] = 0.0f;
#pragma unroll 4
    for (int k = 0; k < K; k++) {
        float w = W[k * M + col];
        const float4* xv = (const float4*)&xs[k * PBR + rg * ROWS];
#pragma unroll
        for (int r4 = 0; r4 < ROWS / 4; r4++) {
            float4 xx = xv[r4];
            acc[r4*4+0] = fmaf(xx.x, w, acc[r4*4+0]);
            acc[r4*4+1] = fmaf(xx.y, w, acc[r4*4+1]);
            acc[r4*4+2] = fmaf(xx.z, w, acc[r4*4+2]);
            acc[r4*4+3] = fmaf(xx.w, w, acc[r4*4+3]);
        }
    }
#pragma unroll
    for (int r = 0; r < ROWS; r++) {
        int row = r0 + rg * ROWS + r;
        if (row < n) Y[row * M + col] = acc[r] * g_dinv[row];
    }
}

// ---------------- CSR gathers (2 nodes/warp, proven) -------------------------
__device__ __forceinline__ float4 h4_to_f4(uint2 raw) {
    const __half2* hp = (const __half2*)&raw;
    float2 a = __half22float2(hp[0]);
    float2 b = __half22float2(hp[1]);
    return make_float4(a.x, a.y, b.x, b.y);
}
__device__ __forceinline__ void acc4(float4& a, float4 v) {
    a.x += v.x; a.y += v.y; a.z += v.z; a.w += v.w;
}

__global__ void gather128_gcn_h(const __half* __restrict__ Hin,
                                float* __restrict__ Hout, int n) {
    int w    = (blockIdx.x * blockDim.x + threadIdx.x) >> 5;
    int lane = threadIdx.x & 31;
    int n0 = 2 * w, n1 = 2 * w + 1;
    if (n0 >= n) return;
    bool has1 = (n1 < n);
    const uint2* H2 = (const uint2*)Hin;
    float4 a0 = h4_to_f4(H2[n0 * 32 + lane]);
    float4 a1 = make_float4(0.f, 0.f, 0.f, 0.f);
    if (has1) a1 = h4_to_f4(H2[n1 * 32 + lane]);
    int e0 = g_off[n0], E0 = g_off[n0 + 1];
    int e1 = has1 ? g_off[n1] : 0, E1 = has1 ? g_off[n1 + 1] : 0;
    while (e0 < E0 && e1 < E1) {
        int i0 = __ldg(&g_csr[e0]); e0++;
        int i1 = __ldg(&g_csr[e1]); e1++;
        acc4(a0, h4_to_f4(H2[i0 * 32 + lane]));
        acc4(a1, h4_to_f4(H2[i1 * 32 + lane]));
    }
    for (; e0 < E0; e0++) acc4(a0, h4_to_f4(H2[__ldg(&g_csr[e0]) * 32 + lane]));
    for (; e1 < E1; e1++) acc4(a1, h4_to_f4(H2[__ldg(&g_csr[e1]) * 32 + lane]));
    float d0 = g_dinv[n0];
    ((float4*)Hout)[n0 * 32 + lane] =
        make_float4(a0.x * d0, a0.y * d0, a0.z * d0, a0.w * d0);
    if (has1) {
        float d1 = g_dinv[n1];
        ((float4*)Hout)[n1 * 32 + lane] =
            make_float4(a1.x * d1, a1.y * d1, a1.z * d1, a1.w * d1);
    }
}

__global__ void gather64_sage_h(const __half* __restrict__ P, const float* __restrict__ Q,
                                float* __restrict__ Y, int n) {
    int w    = (blockIdx.x * blockDim.x + threadIdx.x) >> 5;
    int lane = threadIdx.x & 31;
    int n0 = 2 * w, n1 = 2 * w + 1;
    if (n0 >= n) return;
    bool has1 = (n1 < n);
    const __half2* P2 = (const __half2*)P;
    float2 a0 = make_float2(0.f, 0.f);
    float2 a1 = make_float2(0.f, 0.f);
    int e0 = g_off[n0], E0 = g_off[n0 + 1];
    int e1 = has1 ? g_off[n1] : 0, E1 = has1 ? g_off[n1 + 1] : 0;
    while (e0 < E0 && e1 < E1) {
        int i0 = __ldg(&g_csr[e0]); e0++;
        int i1 = __ldg(&g_csr[e1]); e1++;
        float2 v0 = __half22float2(P2[i0 * 32 + lane]);
        float2 v1 = __half22float2(P2[i1 * 32 + lane]);
        a0.x += v0.x; a0.y += v0.y;
        a1.x += v1.x; a1.y += v1.y;
    }
    for (; e0 < E0; e0++) {
        float2 v = __half22float2(P2[__ldg(&g_csr[e0]) * 32 + lane]);
        a0.x += v.x; a0.y += v.y;
    }
    for (; e1 < E1; e1++) {
        float2 v = __half22float2(P2[__ldg(&g_csr[e1]) * 32 + lane]);
        a1.x += v.x; a1.y += v.y;
    }
    float r0 = g_rcnt[n0];
    float2 q0 = ((const float2*)Q)[n0 * 32 + lane];
    ((float2*)Y)[n0 * 32 + lane] = make_float2(fmaf(a0.x, r0, q0.x), fmaf(a0.y, r0, q0.y));
    if (has1) {
        float r1 = g_rcnt[n1];
        float2 q1 = ((const float2*)Q)[n1 * 32 + lane];
        ((float2*)Y)[n1 * 32 + lane] = make_float2(fmaf(a1.x, r1, q1.x), fmaf(a1.y, r1, q1.y));
    }
}

__global__ void gather32_kernel(const float* __restrict__ Hin,
                                float* __restrict__ Hout, int n) {
    int w    = (blockIdx.x * blockDim.x + threadIdx.x) >> 5;
    int lane = threadIdx.x & 31;
    int n0 = 2 * w, n1 = 2 * w + 1;
    if (n0 >= n) return;
    bool has1 = (n1 < n);
    float a0 = Hin[n0 * 32 + lane];
    float a1 = has1 ? Hin[n1 * 32 + lane] : 0.0f;
    int e0 = g_off[n0], E0 = g_off[n0 + 1];
    int e1 = has1 ? g_off[n1] : 0, E1 = has1 ? g_off[n1 + 1] : 0;
    while (e0 < E0 && e1 < E1) {
        int i0 = __ldg(&g_csr[e0]); e0++;
        int i1 = __ldg(&g_csr[e1]); e1++;
        a0 += Hin[i0 * 32 + lane];
        a1 += Hin[i1 * 32 + lane];
    }
    for (; e0 < E0; e0++) a0 += Hin[__ldg(&g_csr[e0]) * 32 + lane];
    for (; e1 < E1; e1++) a1 += Hin[__ldg(&g_csr[e1]) * 32 + lane];
    Hout[n0 * 32 + lane] = a0 * g_dinv[n0];
    if (has1) Hout[n1 * 32 + lane] = a1 * g_dinv[n1];
}

// F=32 GCN gather + fused pool (no block sync; red.add into g_pool).
__global__ void gather32_pool(const float* __restrict__ Hin,
                              const int* __restrict__ batch,
                              const float* __restrict__ b4, int n) {
    int w    = (blockIdx.x * blockDim.x + threadIdx.x) >> 5;
    int lane = threadIdx.x & 31;
    int n0 = 2 * w, n1 = 2 * w + 1;
    if (n0 >= n) return;
    bool has1 = (n1 < n);
    float bb = b4[lane];
    float a0 = Hin[n0 * 32 + lane];
    float a1 = has1 ? Hin[n1 * 32 + lane] : 0.0f;
    int e0 = g_off[n0], E0 = g_off[n0 + 1];
    int e1 = has1 ? g_off[n1] : 0, E1 = has1 ? g_off[n1 + 1] : 0;
    while (e0 < E0 && e1 < E1) {
        int i0 = __ldg(&g_csr[e0]); e0++;
        int i1 = __ldg(&g_csr[e1]); e1++;
        a0 += Hin[i0 * 32 + lane];
        a1 += Hin[i1 * 32 + lane];
    }
    for (; e0 < E0; e0++) a0 += Hin[__ldg(&g_csr[e0]) * 32 + lane];
    for (; e1 < E1; e1++) a1 += Hin[__ldg(&g_csr[e1]) * 32 + lane];
    {
        float v = fmaf(a0, g_dinv[n0], bb);
        float* p = &g_pool[batch[n0] * 32 + lane];
        asm volatile("red.global.add.f32 [%0], %1;" :: "l"(p), "f"(v) : "memory");
    }
    if (has1) {
        float v = fmaf(a1, g_dinv[n1], bb);
        float* p = &g_pool[batch[n1] * 32 + lane];
        asm volatile("red.global.add.f32 [%0], %1;" :: "l"(p), "f"(v) : "memory");
    }
}

// ---------------- batch norm stats -------------------------------------------
template <int C, int OFF>
__global__ void bn_stats_kernel(const float* __restrict__ X, long long total) {
    __shared__ float s1[256];
    __shared__ float s2[256];
    int tid = threadIdx.x;
    float sum = 0.0f, sq = 0.0f;
    for (long long i = (long long)blockIdx.x * 256 + tid; i < total;
         i += (long long)gridDim.x * 256) {
        float v = X[i];
        sum += v; sq += v * v;
    }
    s1[tid] = sum; s2[tid] = sq;
    __syncthreads();
    for (int off = 128; off >= C; off >>= 1) {
        if (tid < off) { s1[tid] += s1[tid + off]; s2[tid] += s2[tid + off]; }
        __syncthreads();
    }
    if (tid < C) {
        atomicAdd(&g_colsum[OFF + tid], s1[tid]);
        atomicAdd(&g_colsq[OFF + tid],  s2[tid]);
    }
}

// ---------------- link -------------------------------------------------------
__global__ void link_kernel(const int* __restrict__ li, float* __restrict__ out, int L) {
    int w = (blockIdx.x * blockDim.x + threadIdx.x) / 32;
    int lane = threadIdx.x & 31;
    if (w >= L) return;
    int a = li[w], b = li[L + w];
    float v = g_pool[a * 32 + lane] * g_pool[b * 32 + lane];
#pragma unroll
    for (int off = 16; off > 0; off >>= 1)
        v += __shfl_xor_sync(0xFFFFFFFFu, v, off);
    if (lane == 0) out[w] = 1.0f / (1.0f + expf(-v));
}

// ---------------- launch -----------------------------------------------------
extern "C" void kernel_launch(void* const* d_in, const int* in_sizes, int n_in,
                              void* d_out, int out_size) {
    int base = 4;
    if (n_in >= 20 && in_sizes[4] == 1) base = 5;

    const float* x    = (const float*)d_in[0];
    const int*   ei   = (const int*)d_in[1];
    const int*   batch= (const int*)d_in[2];
    const int*   li   = (const int*)d_in[3];
    const float* W1   = (const float*)d_in[base + 0];
    const float* g1   = (const float*)d_in[base + 2];
    const float* be1  = (const float*)d_in[base + 3];
    const float* Wl2  = (const float*)d_in[base + 4];
    const float* Wr2  = (const float*)d_in[base + 6];
    const float* g2   = (const float*)d_in[base + 7];
    const float* be2  = (const float*)d_in[base + 8];
    const float* W3   = (const float*)d_in[base + 9];
    const float* g3   = (const float*)d_in[base + 11];
    const float* be3  = (const float*)d_in[base + 12];
    const float* W4   = (const float*)d_in[base + 13];
    const float* b4   = (const float*)d_in[base + 14];
    float* out = (float*)d_out;

    const int N = in_sizes[0] / 128;
    const int E = in_sizes[1] / 2;
    const int L = in_sizes[3] / 2;
    const int* src = ei;
    const int* dst = ei + E;
    const float invN = 1.0f / (float)N;

    float *bufA, *bufB, *bufC;
    int* indeg;
    cudaGetSymbolAddress((void**)&bufA,  g_bufA);
    cudaGetSymbolAddress((void**)&bufB,  g_bufB);
    cudaGetSymbolAddress((void**)&bufC,  g_bufC);
    cudaGetSymbolAddress((void**)&indeg, g_indeg);
    __half *wh, *whc;
    cudaGetSymbolAddress((void**)&wh,  g_wh);
    cudaGetSymbolAddress((void**)&whc, g_whc);
    __half* bufAh = (__half*)bufA;

    // ---- setup ----
    cudaMemsetAsync(indeg, 0, N * sizeof(int));
    deg_kernel<<<CDIV(E, 1024), 256>>>(dst, E);
    scan_kernel<<<1, 1024>>>(N);                           // + zeros stats/pool
    fill_csr_kernel<<<CDIV(E, 1024), 256>>>(src, dst, E);
    conv_kernel<<<CDIV(2 * 128 * 128, 256), 256>>>(W1, Wl2, Wr2);

    // ---- Layer 1: GCN(128->128) WMMA ----
    gemm1_wmma<<<CDIV(N, 32), 256>>>(x, wh, bufAh, N);
    gather128_gcn_h<<<CDIV(CDIV(N, 2) * 32, 256), 256>>>(bufAh, bufB, N);
    bn_stats_kernel<128, 0><<<1024, 256>>>(bufB, (long long)N * 128);

    // ---- Layer 2: SAGE(128->64) WMMA (BN1 finalized in-block) ----
    dual_gemm_wmma<<<CDIV(N, 32), 256>>>(bufB, whc, g1, be1, invN, bufAh, bufC, N);
    gather64_sage_h<<<CDIV(CDIV(N, 2) * 32, 256), 256>>>(bufAh, bufC, bufB, N);
    bn_stats_kernel<64, 128><<<1024, 256>>>(bufB, (long long)N * 64);

    // ---- Layer 3: GCN(64->32), BN2 finalized in-block ----
    gemm_small<64, 32, 8, 128><<<CDIV(N, 32), 128>>>(bufB, W3, g2, be2, invN, bufA, N);
    gather32_kernel<<<CDIV(CDIV(N, 2) * 32, 256), 256>>>(bufA, bufC, N);
    bn_stats_kernel<32, 192><<<1024, 256>>>(bufC, (long long)N * 32);

    // ---- Layer 4: GCN(32->32), BN3 finalized in-block; pool fused in gather ----
    gemm_small<32, 32, 8, 192><<<CDIV(N, 32), 128>>>(bufC, W4, g3, be3, invN, bufA, N);
    gather32_pool<<<CDIV(CDIV(N, 2) * 32, 256), 256>>>(bufA, batch, b4, N);

    // ---- link ----
    link_kernel<<<CDIV(L * 32, 256), 256>>>(li, out, L);
}